// round 8
// baseline (speedup 1.0000x reference)
#include <cuda_runtime.h>

#define Dv 128
#define Hv 128
#define Wv 128
#define NS 16
#define HS 128
#define WS 128
#define KK 27
#define NITER 10
#define VOLN (Dv*Hv*Wv)
#define HW (Hv*Wv)

// ---- scratch (no allocations allowed) ----
__device__ float g_x[VOLN];
__device__ float g_r[VOLN];
__device__ float g_p[VOLN];
__device__ float g_Apv[VOLN];
__device__ double g_scal[64];   // [0..10]=rr_i, [32..41]=pAp_i

// ---------------------------------------------------------------------------
__device__ __forceinline__ void block_reduce_add(double v, double* target) {
    #pragma unroll
    for (int o = 16; o > 0; o >>= 1) v += __shfl_down_sync(0xffffffffu, v, o);
    __shared__ double sm[32];
    int lane = threadIdx.x & 31, w = threadIdx.x >> 5;
    if (lane == 0) sm[w] = v;
    __syncthreads();
    if (w == 0) {
        v = (lane < (int)(blockDim.x >> 5)) ? sm[lane] : 0.0;
        #pragma unroll
        for (int o = 16; o > 0; o >>= 1) v += __shfl_down_sync(0xffffffffu, v, o);
        if (lane == 0) atomicAdd(target, v);
    }
}

#define SLICE_SHARED_DECL \
    __shared__ float sR[9]; __shared__ float st[3]; \
    __shared__ float sox[KK]; __shared__ float soy[KK]; __shared__ float soz[KK]; \
    __shared__ float spsf[KK];

__device__ __forceinline__ void slice_setup(const float* __restrict__ theta,
                                            const float* __restrict__ psf, int n,
                                            float* sR, float* st,
                                            float* sox, float* soy, float* soz,
                                            float* spsf) {
    int tid = threadIdx.x;
    if (tid < 9)       sR[tid]    = theta[n*12 + (tid/3)*4 + (tid%3)];
    else if (tid < 12) st[tid-9]  = theta[n*12 + (tid-9)*4 + 3] + 63.5f;
    __syncthreads();
    if (tid < KK) {
        float ox = (float)(tid % 3) - 1.f;
        float oy = (float)((tid / 3) % 3) - 1.f;
        float oz = (float)(tid / 9) - 1.f;
        sox[tid] = sR[0]*ox + sR[1]*oy + sR[2]*oz;
        soy[tid] = sR[3]*ox + sR[4]*oy + sR[5]*oz;
        soz[tid] = sR[6]*ox + sR[7]*oy + sR[8]*oz;
        spsf[tid] = psf[tid];
    }
    __syncthreads();
}

// per-pixel base point + tri-state classification.
// Tap cloud radius <= sqrt(3) (rotated (+-1)^3) and trilinear support +1.
// outside: no tap can touch any in-bounds voxel (conservative margin 3.0).
// interior: every tap's full 2^3 cell is strictly in-bounds ([2, 125]).
#define PIXEL_POINT() \
    int pix = blockIdx.x * blockDim.x + threadIdx.x; \
    int iw = pix & (WS - 1); \
    int ih = pix >> 7; \
    float fu = ((float)iw - 63.5f) * 1.5f; \
    float fv = ((float)ih - 63.5f) * 1.5f; \
    float qx = sR[0]*fu + sR[1]*fv + st[0]; \
    float qy = sR[3]*fu + sR[4]*fv + st[1]; \
    float qz = sR[6]*fu + sR[7]*fv + st[2]; \
    bool pout = (qx < -3.f) | (qx > 130.f) | (qy < -3.f) | (qy > 130.f) \
              | (qz < -3.f) | (qz > 130.f); \
    bool pint = (qx > 2.f) & (qx < 125.f) & (qy > 2.f) & (qy < 125.f) \
              & (qz > 2.f) & (qz < 125.f);

// ---- gather taps --------------------------------------------------------
__device__ __forceinline__ float gather_tap_unchecked(const float* __restrict__ vol,
                                                      float px, float py, float pz) {
    float xf = floorf(px), yf = floorf(py), zf = floorf(pz);
    int ix = (int)xf, iy = (int)yf, iz = (int)zf;
    float fx = px - xf, fy = py - yf, fz = pz - zf;
    const float* b0 = vol + ((iz*Hv + iy)*Wv + ix);
    float v000 = __ldg(b0),        v001 = __ldg(b0+1);
    float v010 = __ldg(b0+Wv),     v011 = __ldg(b0+Wv+1);
    float v100 = __ldg(b0+HW),     v101 = __ldg(b0+HW+1);
    float v110 = __ldg(b0+HW+Wv),  v111 = __ldg(b0+HW+Wv+1);
    float c00 = v000 + fx*(v001 - v000);
    float c01 = v010 + fx*(v011 - v010);
    float c10 = v100 + fx*(v101 - v100);
    float c11 = v110 + fx*(v111 - v110);
    float c0 = c00 + fy*(c01 - c00);
    float c1 = c10 + fy*(c11 - c10);
    return c0 + fz*(c1 - c0);
}

__device__ __forceinline__ float gather_tap_checked(const float* __restrict__ vol,
                                                    float px, float py, float pz) {
    float xf = floorf(px), yf = floorf(py), zf = floorf(pz);
    int ix = (int)xf, iy = (int)yf, iz = (int)zf;
    float fx = px - xf, fy = py - yf, fz = pz - zf;
    if (((unsigned)ix < Wv-1u) && ((unsigned)iy < Hv-1u) && ((unsigned)iz < Dv-1u))
        return gather_tap_unchecked(vol, px, py, pz);
    float wx[2] = {1.f - fx, fx}, wy[2] = {1.f - fy, fy}, wz[2] = {1.f - fz, fz};
    float val = 0.f;
    #pragma unroll
    for (int dz = 0; dz < 2; dz++)
    #pragma unroll
    for (int dy = 0; dy < 2; dy++)
    #pragma unroll
    for (int dx = 0; dx < 2; dx++) {
        int xx = ix + dx, yy = iy + dy, zz = iz + dz;
        if (((unsigned)xx < (unsigned)Wv) && ((unsigned)yy < (unsigned)Hv) &&
            ((unsigned)zz < (unsigned)Dv))
            val += wx[dx]*wy[dy]*wz[dz]*__ldg(vol + ((zz*Hv + yy)*Wv + xx));
    }
    return val;
}

// ---- scatter taps -------------------------------------------------------
__device__ __forceinline__ void scatter_tap_unchecked(float* __restrict__ dst,
                                                      float px, float py, float pz, float wv) {
    float xf = floorf(px), yf = floorf(py), zf = floorf(pz);
    int ix = (int)xf, iy = (int)yf, iz = (int)zf;
    float fx = px - xf, fy = py - yf, fz = pz - zf;
    float* b0 = dst + ((iz*Hv + iy)*Wv + ix);
    float wx1 = fx, wx0 = 1.f - fx;
    float w00 = (1.f-fy)*(1.f-fz)*wv, w10 = fy*(1.f-fz)*wv;
    float w01 = (1.f-fy)*fz*wv,       w11 = fy*fz*wv;
    atomicAdd(b0,         wx0*w00); atomicAdd(b0+1,        wx1*w00);
    atomicAdd(b0+Wv,      wx0*w10); atomicAdd(b0+Wv+1,     wx1*w10);
    atomicAdd(b0+HW,      wx0*w01); atomicAdd(b0+HW+1,     wx1*w01);
    atomicAdd(b0+HW+Wv,   wx0*w11); atomicAdd(b0+HW+Wv+1,  wx1*w11);
}

__device__ __forceinline__ void scatter_tap_checked(float* __restrict__ dst,
                                                    float px, float py, float pz, float wv) {
    float xf = floorf(px), yf = floorf(py), zf = floorf(pz);
    int ix = (int)xf, iy = (int)yf, iz = (int)zf;
    float fx = px - xf, fy = py - yf, fz = pz - zf;
    if (((unsigned)ix < Wv-1u) && ((unsigned)iy < Hv-1u) && ((unsigned)iz < Dv-1u)) {
        scatter_tap_unchecked(dst, px, py, pz, wv);
        return;
    }
    float wx[2] = {1.f - fx, fx}, wy[2] = {1.f - fy, fy}, wz[2] = {1.f - fz, fz};
    #pragma unroll
    for (int dz = 0; dz < 2; dz++)
    #pragma unroll
    for (int dy = 0; dy < 2; dy++)
    #pragma unroll
    for (int dx = 0; dx < 2; dx++) {
        int xx = ix + dx, yy = iy + dy, zz = iz + dz;
        if (((unsigned)xx < (unsigned)Wv) && ((unsigned)yy < (unsigned)Hv) &&
            ((unsigned)zz < (unsigned)Dv))
            atomicAdd(dst + ((zz*Hv + yy)*Wv + xx), wx[dx]*wy[dy]*wz[dz]*wv);
    }
}

// ---------------------------------------------------------------------------
// Startup fusion: r += At(slices - A*x0)   (r pre-zeroed; linearity of At)
__global__ void AtA_b_kernel(const float* __restrict__ theta, const float* __restrict__ psf,
                             const float* __restrict__ sl, const float* __restrict__ x0,
                             float* __restrict__ r) {
    SLICE_SHARED_DECL
    const int n = blockIdx.y;
    slice_setup(theta, psf, n, sR, st, sox, soy, soz, spsf);
    PIXEL_POINT()
    if (pout) return;
    float acc = 0.f;
    if (pint) {
        for (int k = 0; k < KK; k++)
            acc += spsf[k] * gather_tap_unchecked(x0, qx + sox[k], qy + soy[k], qz + soz[k]);
    } else {
        for (int k = 0; k < KK; k++)
            acc += spsf[k] * gather_tap_checked(x0, qx + sox[k], qy + soy[k], qz + soz[k]);
    }
    float resid = sl[n*(HS*WS) + pix] - acc;
    if (pint) {
        for (int k = 0; k < KK; k++)
            scatter_tap_unchecked(r, qx + sox[k], qy + soy[k], qz + soz[k], resid * spsf[k]);
    } else {
        for (int k = 0; k < KK; k++)
            scatter_tap_checked(r, qx + sox[k], qy + soy[k], qz + soz[k], resid * spsf[k]);
    }
}

// Fused AtA: acc = (A p)[pixel]; ssq += acc^2; scatter acc back into Apv (pre-zeroed).
__global__ void AtA_kernel(const float* __restrict__ theta, const float* __restrict__ psf,
                           const float* __restrict__ p, float* __restrict__ Apv,
                           double* __restrict__ ssq) {
    SLICE_SHARED_DECL
    const int n = blockIdx.y;
    slice_setup(theta, psf, n, sR, st, sox, soy, soz, spsf);
    PIXEL_POINT()
    float acc = 0.f;
    if (!pout) {
        if (pint) {
            for (int k = 0; k < KK; k++)
                acc += spsf[k] * gather_tap_unchecked(p, qx + sox[k], qy + soy[k], qz + soz[k]);
        } else {
            for (int k = 0; k < KK; k++)
                acc += spsf[k] * gather_tap_checked(p, qx + sox[k], qy + soy[k], qz + soz[k]);
        }
    }
    block_reduce_add((double)acc * (double)acc, ssq);   // all threads: has __syncthreads
    if (!pout && acc != 0.f) {
        if (pint) {
            for (int k = 0; k < KK; k++)
                scatter_tap_unchecked(Apv, qx + sox[k], qy + soy[k], qz + soz[k], acc * spsf[k]);
        } else {
            for (int k = 0; k < KK; k++)
                scatter_tap_checked(Apv, qx + sox[k], qy + soy[k], qz + soz[k], acc * spsf[k]);
        }
    }
}

// Gather-only: ssq += ||A p||^2 (last CG iteration needs only pAp)
__global__ void A_norm_kernel(const float* __restrict__ theta, const float* __restrict__ psf,
                              const float* __restrict__ p, double* __restrict__ ssq) {
    SLICE_SHARED_DECL
    const int n = blockIdx.y;
    slice_setup(theta, psf, n, sR, st, sox, soy, soz, spsf);
    PIXEL_POINT()
    float acc = 0.f;
    if (!pout) {
        if (pint) {
            for (int k = 0; k < KK; k++)
                acc += spsf[k] * gather_tap_unchecked(p, qx + sox[k], qy + soy[k], qz + soz[k]);
        } else {
            for (int k = 0; k < KK; k++)
                acc += spsf[k] * gather_tap_checked(p, qx + sox[k], qy + soy[k], qz + soz[k]);
        }
    }
    block_reduce_add((double)acc * (double)acc, ssq);
}

// ---------------------------------------------------------------------------
#define VPT 4
#define SGRID (VOLN/4/VPT/256)

// p = r; rr0 += ||r||^2; Apv = 0
__global__ void init_pr_kernel(const float4* __restrict__ r, float4* __restrict__ p,
                               float4* __restrict__ Apv, double* __restrict__ rr) {
    int i0 = (blockIdx.x * blockDim.x + threadIdx.x) * VPT;
    double s = 0.0;
    const float4 z = make_float4(0.f, 0.f, 0.f, 0.f);
    #pragma unroll
    for (int j = 0; j < VPT; j++) {
        int i = i0 + j;
        float4 rv = r[i];
        p[i] = rv; Apv[i] = z;
        s += (double)rv.x*rv.x + (double)rv.y*rv.y + (double)rv.z*rv.z + (double)rv.w*rv.w;
    }
    block_reduce_add(s, rr);
}

// r -= alpha*Apv (alpha = rr_old/pAp); rr_new += ||r||^2
__global__ void upd_r_rr_kernel(float4* __restrict__ r, const float4* __restrict__ Apv,
                                const double* __restrict__ rr_old, const double* __restrict__ pAp,
                                double* __restrict__ rr_new) {
    float alpha = (float)(*rr_old / *pAp);
    int i0 = (blockIdx.x * blockDim.x + threadIdx.x) * VPT;
    double s = 0.0;
    #pragma unroll
    for (int j = 0; j < VPT; j++) {
        int i = i0 + j;
        float4 rv = r[i], av = Apv[i];
        rv.x -= alpha*av.x; rv.y -= alpha*av.y; rv.z -= alpha*av.z; rv.w -= alpha*av.w;
        r[i] = rv;
        s += (double)rv.x*rv.x + (double)rv.y*rv.y + (double)rv.z*rv.z + (double)rv.w*rv.w;
    }
    block_reduce_add(s, rr_new);
}

// x += alpha*p; p = r + beta*p; Apv = 0 (for next iteration)
__global__ void pxu_kernel(float4* __restrict__ x, float4* __restrict__ p,
                           const float4* __restrict__ r, float4* __restrict__ Apv,
                           const double* __restrict__ rr_old, const double* __restrict__ pAp,
                           const double* __restrict__ rr_new) {
    float alpha = (float)(*rr_old / *pAp);
    float beta  = (float)(*rr_new / *rr_old);
    int i0 = (blockIdx.x * blockDim.x + threadIdx.x) * VPT;
    const float4 z = make_float4(0.f, 0.f, 0.f, 0.f);
    #pragma unroll
    for (int j = 0; j < VPT; j++) {
        int i = i0 + j;
        float4 xv = x[i], pv = p[i], rv = r[i];
        xv.x += alpha*pv.x; xv.y += alpha*pv.y; xv.z += alpha*pv.z; xv.w += alpha*pv.w;
        x[i] = xv;
        pv.x = rv.x + beta*pv.x; pv.y = rv.y + beta*pv.y;
        pv.z = rv.z + beta*pv.z; pv.w = rv.w + beta*pv.w;
        p[i] = pv;
        Apv[i] = z;
    }
}

// out = relu(x + alpha*p)
__global__ void final_kernel(const float4* __restrict__ x, const float4* __restrict__ p,
                             const double* __restrict__ rr_old, const double* __restrict__ pAp,
                             float4* __restrict__ out) {
    float alpha = (float)(*rr_old / *pAp);
    int i0 = (blockIdx.x * blockDim.x + threadIdx.x) * VPT;
    #pragma unroll
    for (int j = 0; j < VPT; j++) {
        int i = i0 + j;
        float4 xv = x[i], pv = p[i];
        out[i] = make_float4(fmaxf(xv.x + alpha*pv.x, 0.f),
                             fmaxf(xv.y + alpha*pv.y, 0.f),
                             fmaxf(xv.z + alpha*pv.z, 0.f),
                             fmaxf(xv.w + alpha*pv.w, 0.f));
    }
}

// ---------------------------------------------------------------------------
extern "C" void kernel_launch(void* const* d_in, const int* in_sizes, int n_in,
                              void* d_out, int out_size) {
    (void)in_sizes; (void)n_in; (void)out_size;
    const float* theta  = (const float*)d_in[0];
    const float* slices = (const float*)d_in[1];
    const float* volume = (const float*)d_in[2];
    const float* psf    = (const float*)d_in[3];
    float* out = (float*)d_out;

    void *vx, *vr, *vp, *vApv, *vsc;
    cudaGetSymbolAddress(&vx, g_x);
    cudaGetSymbolAddress(&vr, g_r);
    cudaGetSymbolAddress(&vp, g_p);
    cudaGetSymbolAddress(&vApv, g_Apv);
    cudaGetSymbolAddress(&vsc, g_scal);
    float *gx = (float*)vx, *gr = (float*)vr, *gp = (float*)vp, *gApv = (float*)vApv;
    double* gsc = (double*)vsc;

    const dim3 gridS(HS*WS/256, NS);

    cudaMemsetAsync(gsc, 0, 64*sizeof(double), 0);
    cudaMemsetAsync(gr, 0, VOLN*sizeof(float), 0);
    cudaMemcpyAsync(gx, volume, VOLN*sizeof(float), cudaMemcpyDeviceToDevice, 0);

    // r0 = At(slices - A*x0)  [linearity fusion]
    AtA_b_kernel<<<gridS, 256>>>(theta, psf, slices, volume, gr);
    // p = r; rr0; Apv = 0
    init_pr_kernel<<<SGRID, 256>>>((const float4*)gr, (float4*)gp, (float4*)gApv, gsc + 0);

    for (int i = 0; i < NITER - 1; i++) {
        AtA_kernel<<<gridS, 256>>>(theta, psf, gp, gApv, gsc + 32 + i);
        upd_r_rr_kernel<<<SGRID, 256>>>((float4*)gr, (const float4*)gApv,
                                        gsc + i, gsc + 32 + i, gsc + i + 1);
        pxu_kernel<<<SGRID, 256>>>((float4*)gx, (float4*)gp, (const float4*)gr,
                                   (float4*)gApv, gsc + i, gsc + 32 + i, gsc + i + 1);
    }
    // last iteration: only pAp_9 and the x-update matter
    A_norm_kernel<<<gridS, 256>>>(theta, psf, gp, gsc + 32 + NITER - 1);
    final_kernel<<<SGRID, 256>>>((const float4*)gx, (const float4*)gp,
                                 gsc + NITER - 1, gsc + 32 + NITER - 1, (float4*)out);
}

// round 14
// speedup vs baseline: 1.0156x; 1.0156x over previous
#include <cuda_runtime.h>

#define Dv 128
#define Hv 128
#define Wv 128
#define NS 16
#define HS 128
#define WS 128
#define KK 27
#define NITER 10
#define VOLN (Dv*Hv*Wv)
#define HW (Hv*Wv)

// ---- scratch (no allocations allowed) ----
__device__ float g_x[VOLN];
__device__ float g_r[VOLN];
__device__ float g_p[VOLN];
__device__ float g_Apv[VOLN];
__device__ double g_scal[64];   // [0..10]=rr_i, [32..41]=pAp_i

// ---------------------------------------------------------------------------
__device__ __forceinline__ void block_reduce_add(double v, double* target) {
    #pragma unroll
    for (int o = 16; o > 0; o >>= 1) v += __shfl_down_sync(0xffffffffu, v, o);
    __shared__ double sm[32];
    int lane = threadIdx.x & 31, w = threadIdx.x >> 5;
    if (lane == 0) sm[w] = v;
    __syncthreads();
    if (w == 0) {
        v = (lane < (int)(blockDim.x >> 5)) ? sm[lane] : 0.0;
        #pragma unroll
        for (int o = 16; o > 0; o >>= 1) v += __shfl_down_sync(0xffffffffu, v, o);
        if (lane == 0) atomicAdd(target, v);
    }
}

#define SLICE_SHARED_DECL \
    __shared__ float sR[9]; __shared__ float st[3]; \
    __shared__ float sox[KK]; __shared__ float soy[KK]; __shared__ float soz[KK]; \
    __shared__ float spsf[KK];

__device__ __forceinline__ void slice_setup(const float* __restrict__ theta,
                                            const float* __restrict__ psf, int n,
                                            float* sR, float* st,
                                            float* sox, float* soy, float* soz,
                                            float* spsf) {
    int tid = threadIdx.x;
    if (tid < 9)       sR[tid]    = theta[n*12 + (tid/3)*4 + (tid%3)];
    else if (tid < 12) st[tid-9]  = theta[n*12 + (tid-9)*4 + 3] + 63.5f;
    __syncthreads();
    if (tid < KK) {
        float ox = (float)(tid % 3) - 1.f;
        float oy = (float)((tid / 3) % 3) - 1.f;
        float oz = (float)(tid / 9) - 1.f;
        sox[tid] = sR[0]*ox + sR[1]*oy + sR[2]*oz;
        soy[tid] = sR[3]*ox + sR[4]*oy + sR[5]*oz;
        soz[tid] = sR[6]*ox + sR[7]*oy + sR[8]*oz;
        spsf[tid] = psf[tid];
    }
    __syncthreads();
}

// Row-interleaved pixel mapping: 512-thread block b covers rows
// {b, b+32, b+64, b+96}  -> balanced inside/outside mix per CTA.
// Warps stay within one row (32 consecutive iw): gather locality and
// classification coherence preserved.
// Tri-state: outside margin 3.0 > sqrt(3)+1 tap reach; interior window (2,125)
// guarantees every tap's full 2^3 cell is in-bounds.
#define PIXEL_POINT() \
    int t = threadIdx.x; \
    int iw = t & (WS - 1); \
    int ih = blockIdx.x + ((t >> 7) << 5); \
    int pix = ih * WS + iw; \
    float fu = ((float)iw - 63.5f) * 1.5f; \
    float fv = ((float)ih - 63.5f) * 1.5f; \
    float qx = sR[0]*fu + sR[1]*fv + st[0]; \
    float qy = sR[3]*fu + sR[4]*fv + st[1]; \
    float qz = sR[6]*fu + sR[7]*fv + st[2]; \
    bool pout = (qx < -3.f) | (qx > 130.f) | (qy < -3.f) | (qy > 130.f) \
              | (qz < -3.f) | (qz > 130.f); \
    bool pint = (qx > 2.f) & (qx < 125.f) & (qy > 2.f) & (qy < 125.f) \
              & (qz > 2.f) & (qz < 125.f);

// ---- gather taps --------------------------------------------------------
__device__ __forceinline__ float gather_tap_unchecked(const float* __restrict__ vol,
                                                      float px, float py, float pz) {
    float xf = floorf(px), yf = floorf(py), zf = floorf(pz);
    int ix = (int)xf, iy = (int)yf, iz = (int)zf;
    float fx = px - xf, fy = py - yf, fz = pz - zf;
    const float* b0 = vol + ((iz*Hv + iy)*Wv + ix);
    float v000 = __ldg(b0),        v001 = __ldg(b0+1);
    float v010 = __ldg(b0+Wv),     v011 = __ldg(b0+Wv+1);
    float v100 = __ldg(b0+HW),     v101 = __ldg(b0+HW+1);
    float v110 = __ldg(b0+HW+Wv),  v111 = __ldg(b0+HW+Wv+1);
    float c00 = v000 + fx*(v001 - v000);
    float c01 = v010 + fx*(v011 - v010);
    float c10 = v100 + fx*(v101 - v100);
    float c11 = v110 + fx*(v111 - v110);
    float c0 = c00 + fy*(c01 - c00);
    float c1 = c10 + fy*(c11 - c10);
    return c0 + fz*(c1 - c0);
}

__device__ __forceinline__ float gather_tap_checked(const float* __restrict__ vol,
                                                    float px, float py, float pz) {
    float xf = floorf(px), yf = floorf(py), zf = floorf(pz);
    int ix = (int)xf, iy = (int)yf, iz = (int)zf;
    float fx = px - xf, fy = py - yf, fz = pz - zf;
    if (((unsigned)ix < Wv-1u) && ((unsigned)iy < Hv-1u) && ((unsigned)iz < Dv-1u))
        return gather_tap_unchecked(vol, px, py, pz);
    float wx[2] = {1.f - fx, fx}, wy[2] = {1.f - fy, fy}, wz[2] = {1.f - fz, fz};
    float val = 0.f;
    #pragma unroll
    for (int dz = 0; dz < 2; dz++)
    #pragma unroll
    for (int dy = 0; dy < 2; dy++)
    #pragma unroll
    for (int dx = 0; dx < 2; dx++) {
        int xx = ix + dx, yy = iy + dy, zz = iz + dz;
        if (((unsigned)xx < (unsigned)Wv) && ((unsigned)yy < (unsigned)Hv) &&
            ((unsigned)zz < (unsigned)Dv))
            val += wx[dx]*wy[dy]*wz[dz]*__ldg(vol + ((zz*Hv + yy)*Wv + xx));
    }
    return val;
}

// ---- scatter taps -------------------------------------------------------
__device__ __forceinline__ void scatter_tap_unchecked(float* __restrict__ dst,
                                                      float px, float py, float pz, float wv) {
    float xf = floorf(px), yf = floorf(py), zf = floorf(pz);
    int ix = (int)xf, iy = (int)yf, iz = (int)zf;
    float fx = px - xf, fy = py - yf, fz = pz - zf;
    float* b0 = dst + ((iz*Hv + iy)*Wv + ix);
    float wx1 = fx, wx0 = 1.f - fx;
    float w00 = (1.f-fy)*(1.f-fz)*wv, w10 = fy*(1.f-fz)*wv;
    float w01 = (1.f-fy)*fz*wv,       w11 = fy*fz*wv;
    atomicAdd(b0,         wx0*w00); atomicAdd(b0+1,        wx1*w00);
    atomicAdd(b0+Wv,      wx0*w10); atomicAdd(b0+Wv+1,     wx1*w10);
    atomicAdd(b0+HW,      wx0*w01); atomicAdd(b0+HW+1,     wx1*w01);
    atomicAdd(b0+HW+Wv,   wx0*w11); atomicAdd(b0+HW+Wv+1,  wx1*w11);
}

__device__ __forceinline__ void scatter_tap_checked(float* __restrict__ dst,
                                                    float px, float py, float pz, float wv) {
    float xf = floorf(px), yf = floorf(py), zf = floorf(pz);
    int ix = (int)xf, iy = (int)yf, iz = (int)zf;
    float fx = px - xf, fy = py - yf, fz = pz - zf;
    if (((unsigned)ix < Wv-1u) && ((unsigned)iy < Hv-1u) && ((unsigned)iz < Dv-1u)) {
        scatter_tap_unchecked(dst, px, py, pz, wv);
        return;
    }
    float wx[2] = {1.f - fx, fx}, wy[2] = {1.f - fy, fy}, wz[2] = {1.f - fz, fz};
    #pragma unroll
    for (int dz = 0; dz < 2; dz++)
    #pragma unroll
    for (int dy = 0; dy < 2; dy++)
    #pragma unroll
    for (int dx = 0; dx < 2; dx++) {
        int xx = ix + dx, yy = iy + dy, zz = iz + dz;
        if (((unsigned)xx < (unsigned)Wv) && ((unsigned)yy < (unsigned)Hv) &&
            ((unsigned)zz < (unsigned)Dv))
            atomicAdd(dst + ((zz*Hv + yy)*Wv + xx), wx[dx]*wy[dy]*wz[dz]*wv);
    }
}

// ---------------------------------------------------------------------------
// Startup fusion: r += At(slices - A*x0)   (r pre-zeroed; linearity of At)
__global__ void AtA_b_kernel(const float* __restrict__ theta, const float* __restrict__ psf,
                             const float* __restrict__ sl, const float* __restrict__ x0,
                             float* __restrict__ r) {
    SLICE_SHARED_DECL
    const int n = blockIdx.y;
    slice_setup(theta, psf, n, sR, st, sox, soy, soz, spsf);
    PIXEL_POINT()
    if (pout) return;
    float acc = 0.f;
    if (pint) {
        for (int k = 0; k < KK; k++)
            acc += spsf[k] * gather_tap_unchecked(x0, qx + sox[k], qy + soy[k], qz + soz[k]);
    } else {
        for (int k = 0; k < KK; k++)
            acc += spsf[k] * gather_tap_checked(x0, qx + sox[k], qy + soy[k], qz + soz[k]);
    }
    float resid = sl[n*(HS*WS) + pix] - acc;
    if (pint) {
        for (int k = 0; k < KK; k++)
            scatter_tap_unchecked(r, qx + sox[k], qy + soy[k], qz + soz[k], resid * spsf[k]);
    } else {
        for (int k = 0; k < KK; k++)
            scatter_tap_checked(r, qx + sox[k], qy + soy[k], qz + soz[k], resid * spsf[k]);
    }
}

// Fused AtA: acc = (A p)[pixel]; ssq += acc^2; scatter acc back into Apv (pre-zeroed).
__global__ void AtA_kernel(const float* __restrict__ theta, const float* __restrict__ psf,
                           const float* __restrict__ p, float* __restrict__ Apv,
                           double* __restrict__ ssq) {
    SLICE_SHARED_DECL
    const int n = blockIdx.y;
    slice_setup(theta, psf, n, sR, st, sox, soy, soz, spsf);
    PIXEL_POINT()
    float acc = 0.f;
    if (!pout) {
        if (pint) {
            for (int k = 0; k < KK; k++)
                acc += spsf[k] * gather_tap_unchecked(p, qx + sox[k], qy + soy[k], qz + soz[k]);
        } else {
            for (int k = 0; k < KK; k++)
                acc += spsf[k] * gather_tap_checked(p, qx + sox[k], qy + soy[k], qz + soz[k]);
        }
    }
    block_reduce_add((double)acc * (double)acc, ssq);   // all threads: has __syncthreads
    if (!pout && acc != 0.f) {
        if (pint) {
            for (int k = 0; k < KK; k++)
                scatter_tap_unchecked(Apv, qx + sox[k], qy + soy[k], qz + soz[k], acc * spsf[k]);
        } else {
            for (int k = 0; k < KK; k++)
                scatter_tap_checked(Apv, qx + sox[k], qy + soy[k], qz + soz[k], acc * spsf[k]);
        }
    }
}

// Gather-only: ssq += ||A p||^2 (last CG iteration needs only pAp)
__global__ void A_norm_kernel(const float* __restrict__ theta, const float* __restrict__ psf,
                              const float* __restrict__ p, double* __restrict__ ssq) {
    SLICE_SHARED_DECL
    const int n = blockIdx.y;
    slice_setup(theta, psf, n, sR, st, sox, soy, soz, spsf);
    PIXEL_POINT()
    float acc = 0.f;
    if (!pout) {
        if (pint) {
            for (int k = 0; k < KK; k++)
                acc += spsf[k] * gather_tap_unchecked(p, qx + sox[k], qy + soy[k], qz + soz[k]);
        } else {
            for (int k = 0; k < KK; k++)
                acc += spsf[k] * gather_tap_checked(p, qx + sox[k], qy + soy[k], qz + soz[k]);
        }
    }
    block_reduce_add((double)acc * (double)acc, ssq);
}

// ---------------------------------------------------------------------------
#define VPT 4
#define SGRID (VOLN/4/VPT/256)

// p = r; rr0 += ||r||^2
__global__ void init_pr_kernel(const float4* __restrict__ r, float4* __restrict__ p,
                               double* __restrict__ rr) {
    int i0 = (blockIdx.x * blockDim.x + threadIdx.x) * VPT;
    double s = 0.0;
    #pragma unroll
    for (int j = 0; j < VPT; j++) {
        int i = i0 + j;
        float4 rv = r[i];
        p[i] = rv;
        s += (double)rv.x*rv.x + (double)rv.y*rv.y + (double)rv.z*rv.z + (double)rv.w*rv.w;
    }
    block_reduce_add(s, rr);
}

// r -= alpha*Apv (alpha = rr_old/pAp); rr_new += ||r||^2
__global__ void upd_r_rr_kernel(float4* __restrict__ r, const float4* __restrict__ Apv,
                                const double* __restrict__ rr_old, const double* __restrict__ pAp,
                                double* __restrict__ rr_new) {
    float alpha = (float)(*rr_old / *pAp);
    int i0 = (blockIdx.x * blockDim.x + threadIdx.x) * VPT;
    double s = 0.0;
    #pragma unroll
    for (int j = 0; j < VPT; j++) {
        int i = i0 + j;
        float4 rv = r[i], av = Apv[i];
        rv.x -= alpha*av.x; rv.y -= alpha*av.y; rv.z -= alpha*av.z; rv.w -= alpha*av.w;
        r[i] = rv;
        s += (double)rv.x*rv.x + (double)rv.y*rv.y + (double)rv.z*rv.z + (double)rv.w*rv.w;
    }
    block_reduce_add(s, rr_new);
}

// x += alpha*p; p = r + beta*p
__global__ void pxu_kernel(float4* __restrict__ x, float4* __restrict__ p,
                           const float4* __restrict__ r,
                           const double* __restrict__ rr_old, const double* __restrict__ pAp,
                           const double* __restrict__ rr_new) {
    float alpha = (float)(*rr_old / *pAp);
    float beta  = (float)(*rr_new / *rr_old);
    int i0 = (blockIdx.x * blockDim.x + threadIdx.x) * VPT;
    #pragma unroll
    for (int j = 0; j < VPT; j++) {
        int i = i0 + j;
        float4 xv = x[i], pv = p[i], rv = r[i];
        xv.x += alpha*pv.x; xv.y += alpha*pv.y; xv.z += alpha*pv.z; xv.w += alpha*pv.w;
        x[i] = xv;
        pv.x = rv.x + beta*pv.x; pv.y = rv.y + beta*pv.y;
        pv.z = rv.z + beta*pv.z; pv.w = rv.w + beta*pv.w;
        p[i] = pv;
    }
}

// out = relu(x + alpha*p)
__global__ void final_kernel(const float4* __restrict__ x, const float4* __restrict__ p,
                             const double* __restrict__ rr_old, const double* __restrict__ pAp,
                             float4* __restrict__ out) {
    float alpha = (float)(*rr_old / *pAp);
    int i0 = (blockIdx.x * blockDim.x + threadIdx.x) * VPT;
    #pragma unroll
    for (int j = 0; j < VPT; j++) {
        int i = i0 + j;
        float4 xv = x[i], pv = p[i];
        out[i] = make_float4(fmaxf(xv.x + alpha*pv.x, 0.f),
                             fmaxf(xv.y + alpha*pv.y, 0.f),
                             fmaxf(xv.z + alpha*pv.z, 0.f),
                             fmaxf(xv.w + alpha*pv.w, 0.f));
    }
}

// ---------------------------------------------------------------------------
extern "C" void kernel_launch(void* const* d_in, const int* in_sizes, int n_in,
                              void* d_out, int out_size) {
    (void)in_sizes; (void)n_in; (void)out_size;
    const float* theta  = (const float*)d_in[0];
    const float* slices = (const float*)d_in[1];
    const float* volume = (const float*)d_in[2];
    const float* psf    = (const float*)d_in[3];
    float* out = (float*)d_out;

    void *vx, *vr, *vp, *vApv, *vsc;
    cudaGetSymbolAddress(&vx, g_x);
    cudaGetSymbolAddress(&vr, g_r);
    cudaGetSymbolAddress(&vp, g_p);
    cudaGetSymbolAddress(&vApv, g_Apv);
    cudaGetSymbolAddress(&vsc, g_scal);
    float *gx = (float*)vx, *gr = (float*)vr, *gp = (float*)vp, *gApv = (float*)vApv;
    double* gsc = (double*)vsc;

    // Big kernels: 512-thread blocks, 32 x-blocks (4 interleaved rows each), 16 slices
    const dim3 gridS(HS/4, NS);
    const int BIGT = 512;

    cudaMemsetAsync(gsc, 0, 64*sizeof(double), 0);
    cudaMemsetAsync(gr, 0, VOLN*sizeof(float), 0);
    cudaMemcpyAsync(gx, volume, VOLN*sizeof(float), cudaMemcpyDeviceToDevice, 0);

    // r0 = At(slices - A*x0)  [linearity fusion]
    AtA_b_kernel<<<gridS, BIGT>>>(theta, psf, slices, volume, gr);
    // p = r; rr0
    init_pr_kernel<<<SGRID, 256>>>((const float4*)gr, (float4*)gp, gsc + 0);

    for (int i = 0; i < NITER - 1; i++) {
        cudaMemsetAsync(gApv, 0, VOLN*sizeof(float), 0);
        AtA_kernel<<<gridS, BIGT>>>(theta, psf, gp, gApv, gsc + 32 + i);
        upd_r_rr_kernel<<<SGRID, 256>>>((float4*)gr, (const float4*)gApv,
                                        gsc + i, gsc + 32 + i, gsc + i + 1);
        pxu_kernel<<<SGRID, 256>>>((float4*)gx, (float4*)gp, (const float4*)gr,
                                   gsc + i, gsc + 32 + i, gsc + i + 1);
    }
    // last iteration: only pAp_9 and the x-update matter
    A_norm_kernel<<<gridS, BIGT>>>(theta, psf, gp, gsc + 32 + NITER - 1);
    final_kernel<<<SGRID, 256>>>((const float4*)gx, (const float4*)gp,
                                 gsc + NITER - 1, gsc + 32 + NITER - 1, (float4*)out);
}

// round 15
// speedup vs baseline: 1.0985x; 1.0816x over previous
#include <cuda_runtime.h>

#define Dv 128
#define Hv 128
#define Wv 128
#define NS 16
#define HS 128
#define WS 128
#define KK 27
#define NITER 10
#define VOLN (Dv*Hv*Wv)
#define HW (Hv*Wv)

// ---- scratch (no allocations allowed) ----
__device__ float g_x[VOLN];
__device__ float g_r[VOLN];
__device__ float g_p[VOLN];
__device__ float g_Apv[VOLN];
__device__ double g_scal[64];   // [0..10]=rr_i, [32..41]=pAp_i

// ---------------------------------------------------------------------------
__device__ __forceinline__ void block_reduce_add(double v, double* target) {
    #pragma unroll
    for (int o = 16; o > 0; o >>= 1) v += __shfl_down_sync(0xffffffffu, v, o);
    __shared__ double sm[32];
    int lane = threadIdx.x & 31, w = threadIdx.x >> 5;
    if (lane == 0) sm[w] = v;
    __syncthreads();
    if (w == 0) {
        v = (lane < (int)(blockDim.x >> 5)) ? sm[lane] : 0.0;
        #pragma unroll
        for (int o = 16; o > 0; o >>= 1) v += __shfl_down_sync(0xffffffffu, v, o);
        if (lane == 0) atomicAdd(target, v);
    }
}

#define SLICE_SHARED_DECL \
    __shared__ float sR[9]; __shared__ float st[3]; \
    __shared__ float sox[KK]; __shared__ float soy[KK]; __shared__ float soz[KK]; \
    __shared__ float spsf[KK];

__device__ __forceinline__ void slice_setup(const float* __restrict__ theta,
                                            const float* __restrict__ psf, int n,
                                            float* sR, float* st,
                                            float* sox, float* soy, float* soz,
                                            float* spsf) {
    int tid = threadIdx.x;
    if (tid < 9)       sR[tid]    = theta[n*12 + (tid/3)*4 + (tid%3)];
    else if (tid < 12) st[tid-9]  = theta[n*12 + (tid-9)*4 + 3] + 63.5f;
    __syncthreads();
    if (tid < KK) {
        float ox = (float)(tid % 3) - 1.f;
        float oy = (float)((tid / 3) % 3) - 1.f;
        float oz = (float)(tid / 9) - 1.f;
        sox[tid] = sR[0]*ox + sR[1]*oy + sR[2]*oz;
        soy[tid] = sR[3]*ox + sR[4]*oy + sR[5]*oz;
        soz[tid] = sR[6]*ox + sR[7]*oy + sR[8]*oz;
        spsf[tid] = psf[tid];
    }
    __syncthreads();
}

// per-pixel base point in volume coords (R4 mapping: 256-thread contiguous)
#define PIXEL_POINT() \
    int pix = blockIdx.x * blockDim.x + threadIdx.x; \
    int iw = pix & (WS - 1); \
    int ih = pix >> 7; \
    float fu = ((float)iw - 63.5f) * 1.5f; \
    float fv = ((float)ih - 63.5f) * 1.5f; \
    float qx = sR[0]*fu + sR[1]*fv + st[0]; \
    float qy = sR[3]*fu + sR[4]*fv + st[1]; \
    float qz = sR[6]*fu + sR[7]*fv + st[2];

// one trilinear gather tap (R4 form: fast in-bounds path + predicated slow path)
__device__ __forceinline__ float gather_tap(const float* __restrict__ vol,
                                            float px, float py, float pz) {
    float xf = floorf(px), yf = floorf(py), zf = floorf(pz);
    int ix = (int)xf, iy = (int)yf, iz = (int)zf;
    float fx = px - xf, fy = py - yf, fz = pz - zf;
    if (((unsigned)ix < Wv-1u) && ((unsigned)iy < Hv-1u) && ((unsigned)iz < Dv-1u)) {
        const float* b0 = vol + ((iz*Hv + iy)*Wv + ix);
        float v000 = __ldg(b0),        v001 = __ldg(b0+1);
        float v010 = __ldg(b0+Wv),     v011 = __ldg(b0+Wv+1);
        float v100 = __ldg(b0+HW),     v101 = __ldg(b0+HW+1);
        float v110 = __ldg(b0+HW+Wv),  v111 = __ldg(b0+HW+Wv+1);
        float c00 = v000 + fx*(v001 - v000);
        float c01 = v010 + fx*(v011 - v010);
        float c10 = v100 + fx*(v101 - v100);
        float c11 = v110 + fx*(v111 - v110);
        float c0 = c00 + fy*(c01 - c00);
        float c1 = c10 + fy*(c11 - c10);
        return c0 + fz*(c1 - c0);
    }
    float wx[2] = {1.f - fx, fx}, wy[2] = {1.f - fy, fy}, wz[2] = {1.f - fz, fz};
    float val = 0.f;
    #pragma unroll
    for (int dz = 0; dz < 2; dz++)
    #pragma unroll
    for (int dy = 0; dy < 2; dy++)
    #pragma unroll
    for (int dx = 0; dx < 2; dx++) {
        int xx = ix + dx, yy = iy + dy, zz = iz + dz;
        if (((unsigned)xx < (unsigned)Wv) && ((unsigned)yy < (unsigned)Hv) &&
            ((unsigned)zz < (unsigned)Dv))
            val += wx[dx]*wy[dy]*wz[dz]*__ldg(vol + ((zz*Hv + yy)*Wv + xx));
    }
    return val;
}

// one trilinear scatter tap (atomic; R4 form)
__device__ __forceinline__ void scatter_tap(float* __restrict__ dst,
                                            float px, float py, float pz, float wv) {
    float xf = floorf(px), yf = floorf(py), zf = floorf(pz);
    int ix = (int)xf, iy = (int)yf, iz = (int)zf;
    float fx = px - xf, fy = py - yf, fz = pz - zf;
    if (((unsigned)ix < Wv-1u) && ((unsigned)iy < Hv-1u) && ((unsigned)iz < Dv-1u)) {
        float* b0 = dst + ((iz*Hv + iy)*Wv + ix);
        float wx1 = fx, wx0 = 1.f - fx;
        float w00 = (1.f-fy)*(1.f-fz)*wv, w10 = fy*(1.f-fz)*wv;
        float w01 = (1.f-fy)*fz*wv,       w11 = fy*fz*wv;
        atomicAdd(b0,         wx0*w00); atomicAdd(b0+1,        wx1*w00);
        atomicAdd(b0+Wv,      wx0*w10); atomicAdd(b0+Wv+1,     wx1*w10);
        atomicAdd(b0+HW,      wx0*w01); atomicAdd(b0+HW+1,     wx1*w01);
        atomicAdd(b0+HW+Wv,   wx0*w11); atomicAdd(b0+HW+Wv+1,  wx1*w11);
    } else {
        float wx[2] = {1.f - fx, fx}, wy[2] = {1.f - fy, fy}, wz[2] = {1.f - fz, fz};
        #pragma unroll
        for (int dz = 0; dz < 2; dz++)
        #pragma unroll
        for (int dy = 0; dy < 2; dy++)
        #pragma unroll
        for (int dx = 0; dx < 2; dx++) {
            int xx = ix + dx, yy = iy + dy, zz = iz + dz;
            if (((unsigned)xx < (unsigned)Wv) && ((unsigned)yy < (unsigned)Hv) &&
                ((unsigned)zz < (unsigned)Dv))
                atomicAdd(dst + ((zz*Hv + yy)*Wv + xx), wx[dx]*wy[dy]*wz[dz]*wv);
        }
    }
}

// ---------------------------------------------------------------------------
// Startup fusion: r += At(slices - A*x0)   (r pre-zeroed; linearity of At)
__global__ void AtA_b_kernel(const float* __restrict__ theta, const float* __restrict__ psf,
                             const float* __restrict__ sl, const float* __restrict__ x0,
                             float* __restrict__ r) {
    SLICE_SHARED_DECL
    const int n = blockIdx.y;
    slice_setup(theta, psf, n, sR, st, sox, soy, soz, spsf);
    PIXEL_POINT()
    float acc = 0.f;
    for (int k = 0; k < KK; k++)
        acc += spsf[k] * gather_tap(x0, qx + sox[k], qy + soy[k], qz + soz[k]);
    float resid = sl[n*(HS*WS) + pix] - acc;
    for (int k = 0; k < KK; k++)
        scatter_tap(r, qx + sox[k], qy + soy[k], qz + soz[k], resid * spsf[k]);
}

// Fused AtA: acc = (A p)[pixel]; ssq += acc^2; scatter acc*psf into Apv (pre-zeroed).
__global__ void AtA_kernel(const float* __restrict__ theta, const float* __restrict__ psf,
                           const float* __restrict__ p, float* __restrict__ Apv,
                           double* __restrict__ ssq) {
    SLICE_SHARED_DECL
    const int n = blockIdx.y;
    slice_setup(theta, psf, n, sR, st, sox, soy, soz, spsf);
    PIXEL_POINT()
    float acc = 0.f;
    for (int k = 0; k < KK; k++)
        acc += spsf[k] * gather_tap(p, qx + sox[k], qy + soy[k], qz + soz[k]);
    block_reduce_add((double)acc * (double)acc, ssq);
    for (int k = 0; k < KK; k++)
        scatter_tap(Apv, qx + sox[k], qy + soy[k], qz + soz[k], acc * spsf[k]);
}

// Gather-only: ssq += ||A p||^2 (last CG iteration needs only pAp)
__global__ void A_norm_kernel(const float* __restrict__ theta, const float* __restrict__ psf,
                              const float* __restrict__ p, double* __restrict__ ssq) {
    SLICE_SHARED_DECL
    const int n = blockIdx.y;
    slice_setup(theta, psf, n, sR, st, sox, soy, soz, spsf);
    PIXEL_POINT()
    float acc = 0.f;
    for (int k = 0; k < KK; k++)
        acc += spsf[k] * gather_tap(p, qx + sox[k], qy + soy[k], qz + soz[k]);
    block_reduce_add((double)acc * (double)acc, ssq);
}

// ---------------------------------------------------------------------------
#define VPT 4
#define SGRID (VOLN/4/VPT/256)

// p = r; rr0 += ||r||^2
__global__ void init_pr_kernel(const float4* __restrict__ r, float4* __restrict__ p,
                               double* __restrict__ rr) {
    int i0 = (blockIdx.x * blockDim.x + threadIdx.x) * VPT;
    double s = 0.0;
    #pragma unroll
    for (int j = 0; j < VPT; j++) {
        int i = i0 + j;
        float4 rv = r[i];
        p[i] = rv;
        s += (double)rv.x*rv.x + (double)rv.y*rv.y + (double)rv.z*rv.z + (double)rv.w*rv.w;
    }
    block_reduce_add(s, rr);
}

// r -= alpha*Apv (alpha = rr_old/pAp); rr_new += ||r||^2
__global__ void upd_r_rr_kernel(float4* __restrict__ r, const float4* __restrict__ Apv,
                                const double* __restrict__ rr_old, const double* __restrict__ pAp,
                                double* __restrict__ rr_new) {
    float alpha = (float)(*rr_old / *pAp);
    int i0 = (blockIdx.x * blockDim.x + threadIdx.x) * VPT;
    double s = 0.0;
    #pragma unroll
    for (int j = 0; j < VPT; j++) {
        int i = i0 + j;
        float4 rv = r[i], av = Apv[i];
        rv.x -= alpha*av.x; rv.y -= alpha*av.y; rv.z -= alpha*av.z; rv.w -= alpha*av.w;
        r[i] = rv;
        s += (double)rv.x*rv.x + (double)rv.y*rv.y + (double)rv.z*rv.z + (double)rv.w*rv.w;
    }
    block_reduce_add(s, rr_new);
}

// x += alpha*p; p = r + beta*p
__global__ void pxu_kernel(float4* __restrict__ x, float4* __restrict__ p,
                           const float4* __restrict__ r,
                           const double* __restrict__ rr_old, const double* __restrict__ pAp,
                           const double* __restrict__ rr_new) {
    float alpha = (float)(*rr_old / *pAp);
    float beta  = (float)(*rr_new / *rr_old);
    int i0 = (blockIdx.x * blockDim.x + threadIdx.x) * VPT;
    #pragma unroll
    for (int j = 0; j < VPT; j++) {
        int i = i0 + j;
        float4 xv = x[i], pv = p[i], rv = r[i];
        xv.x += alpha*pv.x; xv.y += alpha*pv.y; xv.z += alpha*pv.z; xv.w += alpha*pv.w;
        x[i] = xv;
        pv.x = rv.x + beta*pv.x; pv.y = rv.y + beta*pv.y;
        pv.z = rv.z + beta*pv.z; pv.w = rv.w + beta*pv.w;
        p[i] = pv;
    }
}

// out = relu(x + alpha*p)
__global__ void final_kernel(const float4* __restrict__ x, const float4* __restrict__ p,
                             const double* __restrict__ rr_old, const double* __restrict__ pAp,
                             float4* __restrict__ out) {
    float alpha = (float)(*rr_old / *pAp);
    int i0 = (blockIdx.x * blockDim.x + threadIdx.x) * VPT;
    #pragma unroll
    for (int j = 0; j < VPT; j++) {
        int i = i0 + j;
        float4 xv = x[i], pv = p[i];
        out[i] = make_float4(fmaxf(xv.x + alpha*pv.x, 0.f),
                             fmaxf(xv.y + alpha*pv.y, 0.f),
                             fmaxf(xv.z + alpha*pv.z, 0.f),
                             fmaxf(xv.w + alpha*pv.w, 0.f));
    }
}

// ---------------------------------------------------------------------------
extern "C" void kernel_launch(void* const* d_in, const int* in_sizes, int n_in,
                              void* d_out, int out_size) {
    (void)in_sizes; (void)n_in; (void)out_size;
    const float* theta  = (const float*)d_in[0];
    const float* slices = (const float*)d_in[1];
    const float* volume = (const float*)d_in[2];
    const float* psf    = (const float*)d_in[3];
    float* out = (float*)d_out;

    void *vx, *vr, *vp, *vApv, *vsc;
    cudaGetSymbolAddress(&vx, g_x);
    cudaGetSymbolAddress(&vr, g_r);
    cudaGetSymbolAddress(&vp, g_p);
    cudaGetSymbolAddress(&vApv, g_Apv);
    cudaGetSymbolAddress(&vsc, g_scal);
    float *gx = (float*)vx, *gr = (float*)vr, *gp = (float*)vp, *gApv = (float*)vApv;
    double* gsc = (double*)vsc;

    const dim3 gridS(HS*WS/256, NS);   // R4 config: 256-thread contiguous blocks

    cudaMemsetAsync(gsc, 0, 64*sizeof(double), 0);
    cudaMemsetAsync(gr, 0, VOLN*sizeof(float), 0);
    cudaMemcpyAsync(gx, volume, VOLN*sizeof(float), cudaMemcpyDeviceToDevice, 0);

    // r0 = At(slices - A*x0)  [linearity fusion — the one delta vs R4]
    AtA_b_kernel<<<gridS, 256>>>(theta, psf, slices, volume, gr);
    // p = r; rr0
    init_pr_kernel<<<SGRID, 256>>>((const float4*)gr, (float4*)gp, gsc + 0);

    for (int i = 0; i < NITER - 1; i++) {
        cudaMemsetAsync(gApv, 0, VOLN*sizeof(float), 0);
        AtA_kernel<<<gridS, 256>>>(theta, psf, gp, gApv, gsc + 32 + i);
        upd_r_rr_kernel<<<SGRID, 256>>>((float4*)gr, (const float4*)gApv,
                                        gsc + i, gsc + 32 + i, gsc + i + 1);
        pxu_kernel<<<SGRID, 256>>>((float4*)gx, (float4*)gp, (const float4*)gr,
                                   gsc + i, gsc + 32 + i, gsc + i + 1);
    }
    // last iteration: only pAp_9 and the x-update matter
    A_norm_kernel<<<gridS, 256>>>(theta, psf, gp, gsc + 32 + NITER - 1);
    final_kernel<<<SGRID, 256>>>((const float4*)gx, (const float4*)gp,
                                 gsc + NITER - 1, gsc + 32 + NITER - 1, (float4*)out);
}

// round 16
// speedup vs baseline: 1.1321x; 1.0306x over previous
#include <cuda_runtime.h>

#define Dv 128
#define Hv 128
#define Wv 128
#define NS 16
#define HS 128
#define WS 128
#define KK 27
#define NITER 10
#define VOLN (Dv*Hv*Wv)
#define HW (Hv*Wv)

// ---- scratch (no allocations allowed) ----
__device__ float g_x[VOLN];
__device__ float g_r[VOLN];
__device__ float g_p[VOLN];
__device__ float g_Apv[VOLN];
__device__ double g_scal[64];   // [0..10]=rr_i, [32..41]=pAp_i

// ---------------------------------------------------------------------------
__device__ __forceinline__ void block_reduce_add(double v, double* target) {
    #pragma unroll
    for (int o = 16; o > 0; o >>= 1) v += __shfl_down_sync(0xffffffffu, v, o);
    __shared__ double sm[32];
    int lane = threadIdx.x & 31, w = threadIdx.x >> 5;
    if (lane == 0) sm[w] = v;
    __syncthreads();
    if (w == 0) {
        v = (lane < (int)(blockDim.x >> 5)) ? sm[lane] : 0.0;
        #pragma unroll
        for (int o = 16; o > 0; o >>= 1) v += __shfl_down_sync(0xffffffffu, v, o);
        if (lane == 0) atomicAdd(target, v);
    }
}

#define SLICE_SHARED_DECL \
    __shared__ float sR[9]; __shared__ float st[3]; \
    __shared__ float sox[KK]; __shared__ float soy[KK]; __shared__ float soz[KK]; \
    __shared__ float spsf[KK];

__device__ __forceinline__ void slice_setup(const float* __restrict__ theta,
                                            const float* __restrict__ psf, int n,
                                            float* sR, float* st,
                                            float* sox, float* soy, float* soz,
                                            float* spsf) {
    int tid = threadIdx.x;
    if (tid < 9)       sR[tid]    = theta[n*12 + (tid/3)*4 + (tid%3)];
    else if (tid < 12) st[tid-9]  = theta[n*12 + (tid-9)*4 + 3] + 63.5f;
    __syncthreads();
    if (tid < KK) {
        float ox = (float)(tid % 3) - 1.f;
        float oy = (float)((tid / 3) % 3) - 1.f;
        float oz = (float)(tid / 9) - 1.f;
        sox[tid] = sR[0]*ox + sR[1]*oy + sR[2]*oz;
        soy[tid] = sR[3]*ox + sR[4]*oy + sR[5]*oz;
        soz[tid] = sR[6]*ox + sR[7]*oy + sR[8]*oz;
        spsf[tid] = psf[tid];
    }
    __syncthreads();
}

// per-pixel base point in volume coords (R4 mapping: 256-thread contiguous)
#define PIXEL_POINT() \
    int pix = blockIdx.x * blockDim.x + threadIdx.x; \
    int iw = pix & (WS - 1); \
    int ih = pix >> 7; \
    float fu = ((float)iw - 63.5f) * 1.5f; \
    float fv = ((float)ih - 63.5f) * 1.5f; \
    float qx = sR[0]*fu + sR[1]*fv + st[0]; \
    float qy = sR[3]*fu + sR[4]*fv + st[1]; \
    float qz = sR[6]*fu + sR[7]*fv + st[2];

// one trilinear gather tap (R4 form: fast in-bounds path + predicated slow path)
__device__ __forceinline__ float gather_tap(const float* __restrict__ vol,
                                            float px, float py, float pz) {
    float xf = floorf(px), yf = floorf(py), zf = floorf(pz);
    int ix = (int)xf, iy = (int)yf, iz = (int)zf;
    float fx = px - xf, fy = py - yf, fz = pz - zf;
    if (((unsigned)ix < Wv-1u) && ((unsigned)iy < Hv-1u) && ((unsigned)iz < Dv-1u)) {
        const float* b0 = vol + ((iz*Hv + iy)*Wv + ix);
        float v000 = __ldg(b0),        v001 = __ldg(b0+1);
        float v010 = __ldg(b0+Wv),     v011 = __ldg(b0+Wv+1);
        float v100 = __ldg(b0+HW),     v101 = __ldg(b0+HW+1);
        float v110 = __ldg(b0+HW+Wv),  v111 = __ldg(b0+HW+Wv+1);
        float c00 = v000 + fx*(v001 - v000);
        float c01 = v010 + fx*(v011 - v010);
        float c10 = v100 + fx*(v101 - v100);
        float c11 = v110 + fx*(v111 - v110);
        float c0 = c00 + fy*(c01 - c00);
        float c1 = c10 + fy*(c11 - c10);
        return c0 + fz*(c1 - c0);
    }
    float wx[2] = {1.f - fx, fx}, wy[2] = {1.f - fy, fy}, wz[2] = {1.f - fz, fz};
    float val = 0.f;
    #pragma unroll
    for (int dz = 0; dz < 2; dz++)
    #pragma unroll
    for (int dy = 0; dy < 2; dy++)
    #pragma unroll
    for (int dx = 0; dx < 2; dx++) {
        int xx = ix + dx, yy = iy + dy, zz = iz + dz;
        if (((unsigned)xx < (unsigned)Wv) && ((unsigned)yy < (unsigned)Hv) &&
            ((unsigned)zz < (unsigned)Dv))
            val += wx[dx]*wy[dy]*wz[dz]*__ldg(vol + ((zz*Hv + yy)*Wv + xx));
    }
    return val;
}

// one trilinear scatter tap (atomic; R4 form)
__device__ __forceinline__ void scatter_tap(float* __restrict__ dst,
                                            float px, float py, float pz, float wv) {
    float xf = floorf(px), yf = floorf(py), zf = floorf(pz);
    int ix = (int)xf, iy = (int)yf, iz = (int)zf;
    float fx = px - xf, fy = py - yf, fz = pz - zf;
    if (((unsigned)ix < Wv-1u) && ((unsigned)iy < Hv-1u) && ((unsigned)iz < Dv-1u)) {
        float* b0 = dst + ((iz*Hv + iy)*Wv + ix);
        float wx1 = fx, wx0 = 1.f - fx;
        float w00 = (1.f-fy)*(1.f-fz)*wv, w10 = fy*(1.f-fz)*wv;
        float w01 = (1.f-fy)*fz*wv,       w11 = fy*fz*wv;
        atomicAdd(b0,         wx0*w00); atomicAdd(b0+1,        wx1*w00);
        atomicAdd(b0+Wv,      wx0*w10); atomicAdd(b0+Wv+1,     wx1*w10);
        atomicAdd(b0+HW,      wx0*w01); atomicAdd(b0+HW+1,     wx1*w01);
        atomicAdd(b0+HW+Wv,   wx0*w11); atomicAdd(b0+HW+Wv+1,  wx1*w11);
    } else {
        float wx[2] = {1.f - fx, fx}, wy[2] = {1.f - fy, fy}, wz[2] = {1.f - fz, fz};
        #pragma unroll
        for (int dz = 0; dz < 2; dz++)
        #pragma unroll
        for (int dy = 0; dy < 2; dy++)
        #pragma unroll
        for (int dx = 0; dx < 2; dx++) {
            int xx = ix + dx, yy = iy + dy, zz = iz + dz;
            if (((unsigned)xx < (unsigned)Wv) && ((unsigned)yy < (unsigned)Hv) &&
                ((unsigned)zz < (unsigned)Dv))
                atomicAdd(dst + ((zz*Hv + yy)*Wv + xx), wx[dx]*wy[dy]*wz[dz]*wv);
        }
    }
}

// ---------------------------------------------------------------------------
// Startup fusion: r += At(slices - A*x0)   (r pre-zeroed; linearity of At)
__global__ void AtA_b_kernel(const float* __restrict__ theta, const float* __restrict__ psf,
                             const float* __restrict__ sl, const float* __restrict__ x0,
                             float* __restrict__ r) {
    SLICE_SHARED_DECL
    const int n = blockIdx.y;
    slice_setup(theta, psf, n, sR, st, sox, soy, soz, spsf);
    PIXEL_POINT()
    float acc = 0.f;
    for (int k = 0; k < KK; k++)
        acc += spsf[k] * gather_tap(x0, qx + sox[k], qy + soy[k], qz + soz[k]);
    float resid = sl[n*(HS*WS) + pix] - acc;
    for (int k = 0; k < KK; k++)
        scatter_tap(r, qx + sox[k], qy + soy[k], qz + soz[k], resid * spsf[k]);
}

// Fused AtA: acc = (A p)[pixel]; ssq += acc^2; scatter acc*psf into Apv (pre-zeroed).
__global__ void AtA_kernel(const float* __restrict__ theta, const float* __restrict__ psf,
                           const float* __restrict__ p, float* __restrict__ Apv,
                           double* __restrict__ ssq) {
    SLICE_SHARED_DECL
    const int n = blockIdx.y;
    slice_setup(theta, psf, n, sR, st, sox, soy, soz, spsf);
    PIXEL_POINT()
    float acc = 0.f;
    for (int k = 0; k < KK; k++)
        acc += spsf[k] * gather_tap(p, qx + sox[k], qy + soy[k], qz + soz[k]);
    block_reduce_add((double)acc * (double)acc, ssq);
    for (int k = 0; k < KK; k++)
        scatter_tap(Apv, qx + sox[k], qy + soy[k], qz + soz[k], acc * spsf[k]);
}

// Gather-only: ssq += ||A p||^2 (last CG iteration needs only pAp)
__global__ void A_norm_kernel(const float* __restrict__ theta, const float* __restrict__ psf,
                              const float* __restrict__ p, double* __restrict__ ssq) {
    SLICE_SHARED_DECL
    const int n = blockIdx.y;
    slice_setup(theta, psf, n, sR, st, sox, soy, soz, spsf);
    PIXEL_POINT()
    float acc = 0.f;
    for (int k = 0; k < KK; k++)
        acc += spsf[k] * gather_tap(p, qx + sox[k], qy + soy[k], qz + soz[k]);
    block_reduce_add((double)acc * (double)acc, ssq);
}

// ---------------------------------------------------------------------------
// Streaming kernels: grid-stride (coalesced) layout.
#define VPT 4
#define STHREADS 256
#define SGRID (VOLN/4/VPT/STHREADS)
#define SSTRIDE (SGRID*STHREADS)

// p = r; rr0 += ||r||^2
__global__ void init_pr_kernel(const float4* __restrict__ r, float4* __restrict__ p,
                               double* __restrict__ rr) {
    int i = blockIdx.x * blockDim.x + threadIdx.x;
    double s = 0.0;
    #pragma unroll
    for (int j = 0; j < VPT; j++, i += SSTRIDE) {
        float4 rv = r[i];
        p[i] = rv;
        s += (double)rv.x*rv.x + (double)rv.y*rv.y + (double)rv.z*rv.z + (double)rv.w*rv.w;
    }
    block_reduce_add(s, rr);
}

// r -= alpha*Apv (alpha = rr_old/pAp); rr_new += ||r||^2; Apv = 0 (for next iter)
__global__ void upd_r_rr_kernel(float4* __restrict__ r, float4* __restrict__ Apv,
                                const double* __restrict__ rr_old, const double* __restrict__ pAp,
                                double* __restrict__ rr_new) {
    float alpha = (float)(*rr_old / *pAp);
    int i = blockIdx.x * blockDim.x + threadIdx.x;
    double s = 0.0;
    const float4 z = make_float4(0.f, 0.f, 0.f, 0.f);
    #pragma unroll
    for (int j = 0; j < VPT; j++, i += SSTRIDE) {
        float4 rv = r[i], av = Apv[i];
        rv.x -= alpha*av.x; rv.y -= alpha*av.y; rv.z -= alpha*av.z; rv.w -= alpha*av.w;
        r[i] = rv;
        Apv[i] = z;
        s += (double)rv.x*rv.x + (double)rv.y*rv.y + (double)rv.z*rv.z + (double)rv.w*rv.w;
    }
    block_reduce_add(s, rr_new);
}

// x += alpha*p; p = r + beta*p
__global__ void pxu_kernel(float4* __restrict__ x, float4* __restrict__ p,
                           const float4* __restrict__ r,
                           const double* __restrict__ rr_old, const double* __restrict__ pAp,
                           const double* __restrict__ rr_new) {
    float alpha = (float)(*rr_old / *pAp);
    float beta  = (float)(*rr_new / *rr_old);
    int i = blockIdx.x * blockDim.x + threadIdx.x;
    #pragma unroll
    for (int j = 0; j < VPT; j++, i += SSTRIDE) {
        float4 xv = x[i], pv = p[i], rv = r[i];
        xv.x += alpha*pv.x; xv.y += alpha*pv.y; xv.z += alpha*pv.z; xv.w += alpha*pv.w;
        x[i] = xv;
        pv.x = rv.x + beta*pv.x; pv.y = rv.y + beta*pv.y;
        pv.z = rv.z + beta*pv.z; pv.w = rv.w + beta*pv.w;
        p[i] = pv;
    }
}

// out = relu(x + alpha*p)
__global__ void final_kernel(const float4* __restrict__ x, const float4* __restrict__ p,
                             const double* __restrict__ rr_old, const double* __restrict__ pAp,
                             float4* __restrict__ out) {
    float alpha = (float)(*rr_old / *pAp);
    int i = blockIdx.x * blockDim.x + threadIdx.x;
    #pragma unroll
    for (int j = 0; j < VPT; j++, i += SSTRIDE) {
        float4 xv = x[i], pv = p[i];
        out[i] = make_float4(fmaxf(xv.x + alpha*pv.x, 0.f),
                             fmaxf(xv.y + alpha*pv.y, 0.f),
                             fmaxf(xv.z + alpha*pv.z, 0.f),
                             fmaxf(xv.w + alpha*pv.w, 0.f));
    }
}

// ---------------------------------------------------------------------------
extern "C" void kernel_launch(void* const* d_in, const int* in_sizes, int n_in,
                              void* d_out, int out_size) {
    (void)in_sizes; (void)n_in; (void)out_size;
    const float* theta  = (const float*)d_in[0];
    const float* slices = (const float*)d_in[1];
    const float* volume = (const float*)d_in[2];
    const float* psf    = (const float*)d_in[3];
    float* out = (float*)d_out;

    void *vx, *vr, *vp, *vApv, *vsc;
    cudaGetSymbolAddress(&vx, g_x);
    cudaGetSymbolAddress(&vr, g_r);
    cudaGetSymbolAddress(&vp, g_p);
    cudaGetSymbolAddress(&vApv, g_Apv);
    cudaGetSymbolAddress(&vsc, g_scal);
    float *gx = (float*)vx, *gr = (float*)vr, *gp = (float*)vp, *gApv = (float*)vApv;
    double* gsc = (double*)vsc;

    const dim3 gridS(HS*WS/256, NS);   // verified R4 config for big kernels

    cudaMemsetAsync(gsc, 0, 64*sizeof(double), 0);
    cudaMemsetAsync(gr, 0, VOLN*sizeof(float), 0);
    cudaMemsetAsync(gApv, 0, VOLN*sizeof(float), 0);   // once; upd re-zeroes thereafter
    cudaMemcpyAsync(gx, volume, VOLN*sizeof(float), cudaMemcpyDeviceToDevice, 0);

    // r0 = At(slices - A*x0)  [linearity fusion]
    AtA_b_kernel<<<gridS, 256>>>(theta, psf, slices, volume, gr);
    // p = r; rr0
    init_pr_kernel<<<SGRID, STHREADS>>>((const float4*)gr, (float4*)gp, gsc + 0);

    for (int i = 0; i < NITER - 1; i++) {
        AtA_kernel<<<gridS, 256>>>(theta, psf, gp, gApv, gsc + 32 + i);
        upd_r_rr_kernel<<<SGRID, STHREADS>>>((float4*)gr, (float4*)gApv,
                                             gsc + i, gsc + 32 + i, gsc + i + 1);
        pxu_kernel<<<SGRID, STHREADS>>>((float4*)gx, (float4*)gp, (const float4*)gr,
                                        gsc + i, gsc + 32 + i, gsc + i + 1);
    }
    // last iteration: only pAp_9 and the x-update matter
    A_norm_kernel<<<gridS, 256>>>(theta, psf, gp, gsc + 32 + NITER - 1);
    final_kernel<<<SGRID, STHREADS>>>((const float4*)gx, (const float4*)gp,
                                      gsc + NITER - 1, gsc + 32 + NITER - 1, (float4*)out);
}